// round 5
// baseline (speedup 1.0000x reference)
#include <cuda_runtime.h>
#include <cuda_bf16.h>
#include <cstdint>

#define BATCH      131072
#define HID        256
#define SPIKE_DIM  128
#define COORD_DIM  64
#define IN_DIM     192
#define NUM_STEPS  25
#define BETA       0.7f
#define OMB        (1.0f - BETA)

#define TILES      (BATCH / 128)   // 1024
#define XP         100             // u32 stride per X row (96 used; 100%32==4 -> LDSM conflict-free)
#define WP         100
#define DELTA      0.004f          // rigorous bf16 Cauchy-Schwarz error coefficient

// ---------------- device scratch ----------------
__device__ unsigned g_W0b2[HID * WP];          // W0 bf16x2, [j][k2], padded stride
__device__ float    g_wn[HID];                 // ||W0 row j||_2 (fp32)
__device__ float    g_W1T[HID * HID];          // W1T[j][i] = W1[i][j]
__device__ float    g_WcT[HID * COORD_DIM];    // WcT[i][m] = W_out[128+m][i]
__device__ unsigned g_wmax_u, g_bmax_u;
__device__ unsigned g_tile;
__device__ int      g_heavy[BATCH];
__device__ int      g_nheavy;

// ---------------- helpers ----------------
__device__ __forceinline__ uint32_t smem_u32(const void* p) {
    uint32_t a;
    asm("{ .reg .u64 t; cvta.to.shared.u64 t, %1; cvt.u32.u64 %0, t; }" : "=r"(a) : "l"(p));
    return a;
}
__device__ __forceinline__ unsigned pk(float lo, float hi) {
    __nv_bfloat162 h;
    h.x = __float2bfloat16_rn(lo);
    h.y = __float2bfloat16_rn(hi);
    return *reinterpret_cast<unsigned*>(&h);
}
__device__ __forceinline__ void mma16816(float c[4], const unsigned a[4], const unsigned b[2]) {
    asm volatile(
        "mma.sync.aligned.m16n8k16.row.col.f32.bf16.bf16.f32 "
        "{%0,%1,%2,%3}, {%4,%5,%6,%7}, {%8,%9}, {%0,%1,%2,%3};"
        : "+f"(c[0]), "+f"(c[1]), "+f"(c[2]), "+f"(c[3])
        : "r"(a[0]), "r"(a[1]), "r"(a[2]), "r"(a[3]), "r"(b[0]), "r"(b[1]));
}
__device__ __forceinline__ void ldsm4(uint32_t r[4], uint32_t addr) {
    asm volatile("ldmatrix.sync.aligned.m8n8.x4.shared.b16 {%0,%1,%2,%3}, [%4];"
        : "=r"(r[0]), "=r"(r[1]), "=r"(r[2]), "=r"(r[3]) : "r"(addr));
}

// ---------------- prep0: zero init + W0 pack + row norms ----------------
__global__ void k_prep0(const float* __restrict__ W0) {
    int j  = blockIdx.x;     // 0..255
    int k2 = threadIdx.x;    // 0..95
    if (j == 0 && k2 == 0) {
        g_wmax_u = 0u; g_bmax_u = 0u; g_tile = 0u; g_nheavy = 0;
    }
    float a = W0[j * IN_DIM + 2 * k2], b = W0[j * IN_DIM + 2 * k2 + 1];
    g_W0b2[j * WP + k2] = pk(a, b);

    float sq = fmaf(a, a, b * b);
    #pragma unroll
    for (int o = 16; o; o >>= 1) sq += __shfl_xor_sync(~0u, sq, o);
    __shared__ float r3[3];
    if ((k2 & 31) == 0) r3[k2 >> 5] = sq;
    __syncthreads();
    if (k2 == 0) g_wn[j] = sqrtf(r3[0] + r3[1] + r3[2]);
}

// ---------------- prep1: W1 transpose + maxes + W_out slice transpose ----------------
__global__ void k_prep1(const float* __restrict__ W1, const float* __restrict__ b1,
                        const float* __restrict__ W_out) {
    int i = blockIdx.x, j = threadIdx.x;
    float v = W1[i * HID + j];
    g_W1T[j * HID + i] = v;

    float m = fabsf(v);
    #pragma unroll
    for (int off = 16; off; off >>= 1) m = fmaxf(m, __shfl_xor_sync(~0u, m, off));
    __shared__ float sm[8];
    if ((j & 31) == 0) sm[j >> 5] = m;
    __syncthreads();
    if (j < 8) {
        float t = sm[j];
        #pragma unroll
        for (int off = 4; off; off >>= 1) t = fmaxf(t, __shfl_xor_sync(0xffu, t, off));
        if (j == 0) atomicMax(&g_wmax_u, __float_as_uint(t));
    }
    if (i == 0) atomicMax(&g_bmax_u, __float_as_uint(fabsf(b1[j])));
    if (i < COORD_DIM) g_WcT[j * COORD_DIM + i] = W_out[(SPIKE_DIM + i) * HID + j];
}

// ---------------- GEMM + certified classifier + light output ----------------
// smem u32 offsets
#define U_WS  0
#define U_XS  25600
#define U_B0  38400
#define U_WN  38656
#define U_BC  38912
#define U_XN  38976
#define U_CT  39104
#define U_ST  39232
#define GEMM_SMEM ((U_ST + 4) * 4)

__global__ __launch_bounds__(256, 1)
void k_gemm(const float* __restrict__ spikes, const float* __restrict__ coords,
            const float* __restrict__ b0, const float* __restrict__ b_out,
            float* __restrict__ out) {
    extern __shared__ unsigned sh[];
    unsigned* Ws  = sh + U_WS;     // [256][WP]
    unsigned* Xs  = sh + U_XS;     // [128][XP]
    float*    b0s = (float*)(sh + U_B0);
    float*    wns = (float*)(sh + U_WN);
    float*    bcs = (float*)(sh + U_BC);
    float*    xn2 = (float*)(sh + U_XN);   // [128]
    int*      cnt = (int*)(sh + U_CT);     // [128]
    unsigned* stl = sh + U_ST;

    int tid  = threadIdx.x;
    int lane = tid & 31;
    int wid  = tid >> 5;
    int g    = lane >> 2, qp = lane & 3;
    int wm   = wid >> 2,  wn_ = wid & 3;

    // one-time fills
    {
        const float4* src = (const float4*)g_W0b2;
        float4* dst = (float4*)Ws;
        #pragma unroll
        for (int i = 0; i < 25; i++) dst[i * 256 + tid] = src[i * 256 + tid];
        b0s[tid] = b0[tid];
        wns[tid] = g_wn[tid];
        if (tid < 64) bcs[tid] = b_out[SPIKE_DIM + tid];
    }

    // Hlim (inline finalize)
    int Hlim;
    {
        float wmax = __uint_as_float(g_wmax_u);
        float bmax = __uint_as_float(g_bmax_u);
        if (bmax >= 0.995f)    Hlim = -1;
        else if (wmax <= 0.0f) Hlim = 1 << 30;
        else                   Hlim = (int)floorf((0.995f - bmax) / wmax);
    }

    // per-lane ldmatrix base addresses
    uint32_t xs_b = smem_u32(Xs);
    uint32_t ws_b = smem_u32(Ws);
    uint32_t a_base = xs_b + (((wm * 64 + (lane & 15)) * XP) + ((lane >> 4) << 2)) * 4;
    uint32_t b_base = ws_b + ((((lane >> 4) * 8 + (lane & 7)) * WP) + (((lane >> 3) & 1) << 2)) * 4;

    #pragma unroll 1
    for (;;) {
        __syncthreads();
        if (tid == 0) *stl = atomicAdd(&g_tile, 1u);
        if (tid < 128) { xn2[tid] = 0.0f; cnt[tid] = 0; }
        __syncthreads();
        unsigned tile = *stl;
        if (tile >= TILES) break;
        int R0 = (int)tile * 128;

        // ---- X load + bf16 convert + row sumsq (16-lane groups share a row)
        #pragma unroll
        for (int it = 0; it < 24; it++) {
            int idx = it * 256 + tid;
            int row = idx / 48, f4 = idx % 48;
            float4 v;
            if (f4 < 32) v = ((const float4*)(spikes + (size_t)(R0 + row) * SPIKE_DIM))[f4];
            else         v = ((const float4*)(coords + (size_t)(R0 + row) * COORD_DIM))[f4 - 32];
            *(uint2*)(Xs + row * XP + 2 * f4) = make_uint2(pk(v.x, v.y), pk(v.z, v.w));
            float sq = fmaf(v.x, v.x, fmaf(v.y, v.y, fmaf(v.z, v.z, v.w * v.w)));
            #pragma unroll
            for (int o = 8; o; o >>= 1) sq += __shfl_xor_sync(~0u, sq, o);
            if ((lane & 15) == 0) atomicAdd(&xn2[row], sq);
        }
        __syncthreads();

        // per-thread row error margins
        float dx0[4], dx1[4];
        #pragma unroll
        for (int mt = 0; mt < 4; mt++) {
            int r0 = wm * 64 + mt * 16 + g;
            dx0[mt] = DELTA * sqrtf(xn2[r0]);
            dx1[mt] = DELTA * sqrtf(xn2[r0 + 8]);
        }
        int cl[4] = {0, 0, 0, 0}, chn[4] = {0, 0, 0, 0};

        #pragma unroll 1
        for (int h = 0; h < 2; h++) {          // n-halves (32 cols per warp each)
            float cf[4][4][4];
            #pragma unroll
            for (int mt = 0; mt < 4; mt++)
                #pragma unroll
                for (int nt = 0; nt < 4; nt++)
                    #pragma unroll
                    for (int q = 0; q < 4; q++) cf[mt][nt][q] = 0.0f;

            #pragma unroll
            for (int kk = 0; kk < 12; kk++) {
                uint32_t a[4][4], bfr[2][4];
                #pragma unroll
                for (int mt = 0; mt < 4; mt++)
                    ldsm4(a[mt], a_base + (unsigned)((mt * 16 * XP + kk * 8) * 4));
                #pragma unroll
                for (int np = 0; np < 2; np++)
                    ldsm4(bfr[np], b_base + (unsigned)((((wn_ * 64 + h * 32 + np * 16) * WP) + kk * 8) * 4));
                #pragma unroll
                for (int mt = 0; mt < 4; mt++)
                    #pragma unroll
                    for (int nt = 0; nt < 4; nt++)
                        mma16816(cf[mt][nt], a[mt], &bfr[nt >> 1][(nt & 1) * 2]);
            }

            // classifier: cf >= 0.999 - b0[col] - dx[row]*wn[col]
            #pragma unroll
            for (int nt = 0; nt < 4; nt++) {
                int c = wn_ * 64 + h * 32 + nt * 8 + 2 * qp;
                float bA = b0s[c], bB = b0s[c + 1];
                float wA = wns[c], wB = wns[c + 1];
                #pragma unroll
                for (int mt = 0; mt < 4; mt++) {
                    cl[mt]  += (cf[mt][nt][0] >= 0.999f - bA - dx0[mt] * wA) ? 1 : 0;
                    cl[mt]  += (cf[mt][nt][1] >= 0.999f - bB - dx0[mt] * wB) ? 1 : 0;
                    chn[mt] += (cf[mt][nt][2] >= 0.999f - bA - dx1[mt] * wA) ? 1 : 0;
                    chn[mt] += (cf[mt][nt][3] >= 0.999f - bB - dx1[mt] * wB) ? 1 : 0;
                }
            }
        }

        // quad-reduce counts, one atomic per row per warp
        #pragma unroll
        for (int mt = 0; mt < 4; mt++) {
            int s0 = cl[mt], s1 = chn[mt];
            s0 += __shfl_xor_sync(~0u, s0, 1); s0 += __shfl_xor_sync(~0u, s0, 2);
            s1 += __shfl_xor_sync(~0u, s1, 1); s1 += __shfl_xor_sync(~0u, s1, 2);
            if (qp == 0) {
                int r0 = wm * 64 + mt * 16 + g;
                if (s0) atomicAdd(&cnt[r0], s0);
                if (s1) atomicAdd(&cnt[r0 + 8], s1);
            }
        }
        __syncthreads();

        if (tid < 128 && cnt[tid] > Hlim) {
            int pos = atomicAdd(&g_nheavy, 1);
            g_heavy[pos] = R0 + tid;
        }

        // ---- certified light output (heavy rows overwritten by k_heavy)
        float4 z = make_float4(0.f, 0.f, 0.f, 0.f);
        #pragma unroll
        for (int it = 0; it < 32; it++) {
            int idx = it * 256 + tid;
            int row = idx >> 6, f = idx & 63;
            ((float4*)(out + (size_t)(R0 + row) * HID))[f] = z;
        }
        #pragma unroll
        for (int it = 0; it < 8; it++) {
            int idx = it * 256 + tid;
            int row = idx >> 4, f = idx & 15;
            float4 cv = make_float4(bcs[4 * f], bcs[4 * f + 1], bcs[4 * f + 2], bcs[4 * f + 3]);
            ((float4*)(out + (size_t)BATCH * HID + (size_t)(R0 + row) * COORD_DIM))[f] = cv;
        }
    }
}

// ---------------- heavy rows: exact fp32 recompute + simulation ----------------
__global__ void k_heavy(const float* __restrict__ spikes, const float* __restrict__ coords,
                        const float* __restrict__ W0, const float* __restrict__ b0,
                        const float* __restrict__ b1, const float* __restrict__ b_out,
                        float* __restrict__ out) {
    int warps = (gridDim.x * blockDim.x) >> 5;
    int gw    = (blockIdx.x * blockDim.x + threadIdx.x) >> 5;
    int lane  = threadIdx.x & 31;
    int n     = g_nheavy;

    for (int idx = gw; idx < n; idx += warps) {
        int row = g_heavy[idx];
        float* actp = out + (size_t)row * HID;
        float* crdp = out + (size_t)BATCH * HID + (size_t)row * COORD_DIM;

        const float* xs = spikes + (size_t)row * SPIKE_DIM;
        const float* xc = coords + (size_t)row * COORD_DIM;
        float s[8];
        #pragma unroll
        for (int r = 0; r < 8; r++) s[r] = 0.0f;
        #pragma unroll 4
        for (int k = 0; k < SPIKE_DIM; k++) {
            float xv = xs[k];
            #pragma unroll
            for (int r = 0; r < 8; r++)
                s[r] = fmaf(xv, W0[(size_t)(lane + 32 * r) * IN_DIM + k], s[r]);
        }
        #pragma unroll 4
        for (int k = 0; k < COORD_DIM; k++) {
            float xv = xc[k];
            #pragma unroll
            for (int r = 0; r < 8; r++)
                s[r] = fmaf(xv, W0[(size_t)(lane + 32 * r) * IN_DIM + SPIKE_DIM + k], s[r]);
        }

        float q[8], v0[8], v1[8], b1v[8];
        #pragma unroll
        for (int k = 0; k < 8; k++) {
            q[k] = OMB * (s[k] + b0[lane + 32 * k]);
            v0[k] = 0.0f; v1[k] = 0.0f;
            b1v[k] = b1[lane + 32 * k];
        }
        unsigned sp1m[8];
        #pragma unroll
        for (int k = 0; k < 8; k++) sp1m[k] = 0u;

        #pragma unroll 1
        for (int t = 0; t < NUM_STEPS; t++) {
            unsigned act[8];
            #pragma unroll
            for (int k = 0; k < 8; k++) {
                v0[k] = fmaf(BETA, v0[k], q[k]);
                bool sp = (v0[k] >= 1.0f);
                act[k] = __ballot_sync(~0u, sp);
                if (sp) v0[k] = 0.0f;
            }
            float c1[8];
            #pragma unroll
            for (int k = 0; k < 8; k++) c1[k] = b1v[k];
            #pragma unroll
            for (int k = 0; k < 8; k++) {
                unsigned m = act[k];
                while (m) {
                    int j = 32 * k + __ffs(m) - 1;
                    m &= m - 1;
                    const float* wr = g_W1T + (size_t)j * HID;
                    #pragma unroll
                    for (int r = 0; r < 8; r++) c1[r] += wr[lane + 32 * r];
                }
            }
            #pragma unroll
            for (int k = 0; k < 8; k++) {
                v1[k] = fmaf(BETA, v1[k], OMB * c1[k]);
                bool sp = (v1[k] >= 1.0f);
                unsigned b = __ballot_sync(~0u, sp);
                if (t == NUM_STEPS - 1) sp1m[k] = b;
                if (sp) v1[k] = 0.0f;
            }
        }

        #pragma unroll
        for (int k = 0; k < 8; k++)
            actp[lane + 32 * k] = ((sp1m[k] >> lane) & 1u) ? 1.0f : 0.0f;

        float ca = b_out[SPIKE_DIM + lane];
        float cb = b_out[SPIKE_DIM + 32 + lane];
        #pragma unroll
        for (int k = 0; k < 8; k++) {
            unsigned m = sp1m[k];
            while (m) {
                int i = 32 * k + __ffs(m) - 1;
                m &= m - 1;
                ca += g_WcT[(size_t)i * COORD_DIM + lane];
                cb += g_WcT[(size_t)i * COORD_DIM + 32 + lane];
            }
        }
        crdp[lane]      = ca;
        crdp[lane + 32] = cb;
    }
}

// ---------------- launch ----------------
extern "C" void kernel_launch(void* const* d_in, const int* in_sizes, int n_in,
                              void* d_out, int out_size) {
    const float* spikes = (const float*)d_in[0];
    const float* coords = (const float*)d_in[1];
    const float* W0     = (const float*)d_in[2];
    const float* b0     = (const float*)d_in[3];
    const float* W1     = (const float*)d_in[4];
    const float* b1     = (const float*)d_in[5];
    const float* W_out  = (const float*)d_in[6];
    const float* b_out  = (const float*)d_in[7];
    float* out = (float*)d_out;

    k_prep0<<<256, 96>>>(W0);
    k_prep1<<<256, 256>>>(W1, b1, W_out);

    cudaFuncSetAttribute(k_gemm, cudaFuncAttributeMaxDynamicSharedMemorySize, GEMM_SMEM);
    k_gemm<<<148, 256, GEMM_SMEM>>>(spikes, coords, b0, b_out, out);

    k_heavy<<<256, 256>>>(spikes, coords, W0, b0, b1, b_out, out);
}

// round 6
// speedup vs baseline: 2.1403x; 2.1403x over previous
#include <cuda_runtime.h>
#include <cuda_bf16.h>
#include <cstdint>

#define BATCH      131072
#define HID        256
#define SPIKE_DIM  128
#define COORD_DIM  64
#define IN_DIM     192
#define NUM_STEPS  25
#define BETA       0.7f
#define OMB        (1.0f - BETA)

#define TILES      (BATCH / 128)   // 1024
#define XP         100             // u32 stride per X row (96 used; 100%32==4 -> LDSM conflict-free)
#define WP         100
#define DELTA      0.004f          // rigorous bf16 Cauchy-Schwarz error coefficient

// ---------------- device scratch ----------------
__device__ unsigned g_W0b2[HID * WP];          // W0 bf16x2, [j][k2], padded stride
__device__ float    g_W0T[IN_DIM * HID];       // W0T[k][j] = W0[j][k]  (coalesced heavy path)
__device__ float    g_wn[HID];                 // ||W0 row j||_2
__device__ float    g_W1T[HID * HID];          // W1T[j][i] = W1[i][j]
__device__ float    g_WcT[HID * COORD_DIM];    // WcT[i][m] = W_out[128+m][i]
__device__ unsigned g_wmax_u, g_bmax_u;        // static zero-init; monotone max (replay-safe)
__device__ unsigned g_tile;
__device__ int      g_heavy[BATCH];
__device__ int      g_nheavy;

// ---------------- helpers ----------------
__device__ __forceinline__ uint32_t smem_u32(const void* p) {
    uint32_t a;
    asm("{ .reg .u64 t; cvta.to.shared.u64 t, %1; cvt.u32.u64 %0, t; }" : "=r"(a) : "l"(p));
    return a;
}
__device__ __forceinline__ unsigned pk(float lo, float hi) {
    __nv_bfloat162 h;
    h.x = __float2bfloat16_rn(lo);
    h.y = __float2bfloat16_rn(hi);
    return *reinterpret_cast<unsigned*>(&h);
}
__device__ __forceinline__ void mma16816(float c[4], const unsigned a[4], const unsigned b[2]) {
    asm volatile(
        "mma.sync.aligned.m16n8k16.row.col.f32.bf16.bf16.f32 "
        "{%0,%1,%2,%3}, {%4,%5,%6,%7}, {%8,%9}, {%0,%1,%2,%3};"
        : "+f"(c[0]), "+f"(c[1]), "+f"(c[2]), "+f"(c[3])
        : "r"(a[0]), "r"(a[1]), "r"(a[2]), "r"(a[3]), "r"(b[0]), "r"(b[1]));
}
__device__ __forceinline__ void ldsm4(uint32_t r[4], uint32_t addr) {
    asm volatile("ldmatrix.sync.aligned.m8n8.x4.shared.b16 {%0,%1,%2,%3}, [%4];"
        : "=r"(r[0]), "=r"(r[1]), "=r"(r[2]), "=r"(r[3]) : "r"(addr));
}
// rigorous spike-rate weight: upper-bounds 1/(1-beta^(P(c)-1)) for drive <= c
__device__ __forceinline__ float wgt(float c) {
    float d = fmaxf(1.0f - 0.3f * c, 0.2101f);
    return fminf(__fdividef(0.70007f * c, d), 3.3334f);
}

// ---------------- fused prep ----------------
__global__ void k_prep(const float* __restrict__ W0, const float* __restrict__ W1,
                       const float* __restrict__ b1, const float* __restrict__ W_out) {
    int i = blockIdx.x, j = threadIdx.x;
    if (i == 0 && j == 0) { g_tile = 0u; g_nheavy = 0; }

    float v = W1[i * HID + j];
    g_W1T[j * HID + i] = v;

    float m = fabsf(v);
    #pragma unroll
    for (int off = 16; off; off >>= 1) m = fmaxf(m, __shfl_xor_sync(~0u, m, off));
    __shared__ float sm[8];
    __shared__ float r3[3];
    if ((j & 31) == 0) sm[j >> 5] = m;

    if (j < 96) {   // warps 0..2 fully active
        float a = W0[i * IN_DIM + 2 * j], b = W0[i * IN_DIM + 2 * j + 1];
        g_W0b2[i * WP + j] = pk(a, b);
        g_W0T[(2 * j) * HID + i]     = a;
        g_W0T[(2 * j + 1) * HID + i] = b;
        float sq = fmaf(a, a, b * b);
        #pragma unroll
        for (int o = 16; o; o >>= 1) sq += __shfl_xor_sync(~0u, sq, o);
        if ((j & 31) == 0) r3[j >> 5] = sq;
    }
    __syncthreads();
    if (j < 8) {
        float t = sm[j];
        #pragma unroll
        for (int off = 4; off; off >>= 1) t = fmaxf(t, __shfl_xor_sync(0xffu, t, off));
        if (j == 0) atomicMax(&g_wmax_u, __float_as_uint(t));
    }
    if (i == 0) atomicMax(&g_bmax_u, __float_as_uint(fabsf(b1[j])));
    if (j == 0) g_wn[i] = sqrtf(r3[0] + r3[1] + r3[2]);
    if (i < COORD_DIM) g_WcT[j * COORD_DIM + i] = W_out[(SPIKE_DIM + i) * HID + j];
}

// ---------------- GEMM + spike-rate-certified classifier + light output ----------------
#define U_WS  0
#define U_XS  25600
#define U_B0  38400
#define U_WN  38656
#define U_BC  38912
#define U_XN  38976
#define U_SS  39104
#define U_ST  39232
#define GEMM_SMEM ((U_ST + 4) * 4)

__global__ __launch_bounds__(256, 1)
void k_gemm(const float* __restrict__ spikes, const float* __restrict__ coords,
            const float* __restrict__ b0, const float* __restrict__ b_out,
            float* __restrict__ out) {
    extern __shared__ unsigned sh[];
    unsigned* Ws  = sh + U_WS;     // [256][WP]
    unsigned* Xs  = sh + U_XS;     // [128][XP]
    float*    b0s = (float*)(sh + U_B0);
    float*    wns = (float*)(sh + U_WN);
    float*    bcs = (float*)(sh + U_BC);
    float*    xn2 = (float*)(sh + U_XN);   // [128]
    float*    Ss  = (float*)(sh + U_SS);   // [128] spike-rate sums
    unsigned* stl = sh + U_ST;

    int tid  = threadIdx.x;
    int lane = tid & 31;
    int wid  = tid >> 5;
    int g    = lane >> 2, qp = lane & 3;
    int wm   = wid >> 2,  wn_ = wid & 3;

    {
        const float4* src = (const float4*)g_W0b2;
        float4* dst = (float4*)Ws;
        #pragma unroll
        for (int i = 0; i < 25; i++) dst[i * 256 + tid] = src[i * 256 + tid];
        b0s[tid] = b0[tid];
        wns[tid] = g_wn[tid];
        if (tid < 64) bcs[tid] = b_out[SPIKE_DIM + tid];
    }

    // spike-rate limit: light certified iff bmax + OMB*wmax*S < 0.999
    float Slim;
    {
        float wmax = __uint_as_float(g_wmax_u);
        float bmax = __uint_as_float(g_bmax_u);
        if (bmax >= 0.999f)    Slim = -1.0f;          // everything heavy
        else if (wmax <= 0.0f) Slim = 1e30f;          // nothing heavy
        else Slim = __fdividef(0.999f - bmax, 0.3000001f * wmax) * 0.998f - 0.01f;
    }

    uint32_t xs_b = smem_u32(Xs);
    uint32_t ws_b = smem_u32(Ws);
    uint32_t a_base = xs_b + (((wm * 64 + (lane & 15)) * XP) + ((lane >> 4) << 2)) * 4;
    uint32_t b_base = ws_b + ((((lane >> 4) * 8 + (lane & 7)) * WP) + (((lane >> 3) & 1) << 2)) * 4;

    #pragma unroll 1
    for (;;) {
        __syncthreads();
        if (tid == 0) *stl = atomicAdd(&g_tile, 1u);
        if (tid < 128) { xn2[tid] = 0.0f; Ss[tid] = 0.0f; }
        __syncthreads();
        unsigned tile = *stl;
        if (tile >= TILES) break;
        int R0 = (int)tile * 128;

        // ---- X load + bf16 convert + row sumsq
        #pragma unroll
        for (int it = 0; it < 24; it++) {
            int idx = it * 256 + tid;
            int row = idx / 48, f4 = idx % 48;
            float4 v;
            if (f4 < 32) v = ((const float4*)(spikes + (size_t)(R0 + row) * SPIKE_DIM))[f4];
            else         v = ((const float4*)(coords + (size_t)(R0 + row) * COORD_DIM))[f4 - 32];
            *(uint2*)(Xs + row * XP + 2 * f4) = make_uint2(pk(v.x, v.y), pk(v.z, v.w));
            float sq = fmaf(v.x, v.x, fmaf(v.y, v.y, fmaf(v.z, v.z, v.w * v.w)));
            #pragma unroll
            for (int o = 8; o; o >>= 1) sq += __shfl_xor_sync(~0u, sq, o);
            if ((lane & 15) == 0) atomicAdd(&xn2[row], sq);
        }
        __syncthreads();

        float dx0[4], dx1[4];
        #pragma unroll
        for (int mt = 0; mt < 4; mt++) {
            int r0 = wm * 64 + mt * 16 + g;
            dx0[mt] = DELTA * sqrtf(xn2[r0]);
            dx1[mt] = DELTA * sqrtf(xn2[r0 + 8]);
        }
        float sl0[4] = {0.f, 0.f, 0.f, 0.f}, sl1[4] = {0.f, 0.f, 0.f, 0.f};

        #pragma unroll 1
        for (int h = 0; h < 2; h++) {
            float cf[4][4][4];
            #pragma unroll
            for (int mt = 0; mt < 4; mt++)
                #pragma unroll
                for (int nt = 0; nt < 4; nt++)
                    #pragma unroll
                    for (int q = 0; q < 4; q++) cf[mt][nt][q] = 0.0f;

            #pragma unroll
            for (int kk = 0; kk < 12; kk++) {
                uint32_t a[4][4], bfr[2][4];
                #pragma unroll
                for (int mt = 0; mt < 4; mt++)
                    ldsm4(a[mt], a_base + (unsigned)((mt * 16 * XP + kk * 8) * 4));
                #pragma unroll
                for (int np = 0; np < 2; np++)
                    ldsm4(bfr[np], b_base + (unsigned)((((wn_ * 64 + h * 32 + np * 16) * WP) + kk * 8) * 4));
                #pragma unroll
                for (int mt = 0; mt < 4; mt++)
                    #pragma unroll
                    for (int nt = 0; nt < 4; nt++)
                        mma16816(cf[mt][nt], a[mt], &bfr[nt >> 1][(nt & 1) * 2]);
            }

            // certified upper bound c0u = cf + b0 + dx*||w||; accumulate spike-rate weight
            #pragma unroll
            for (int nt = 0; nt < 4; nt++) {
                int c = wn_ * 64 + h * 32 + nt * 8 + 2 * qp;
                float bA = b0s[c], bB = b0s[c + 1];
                float wA = wns[c], wB = wns[c + 1];
                #pragma unroll
                for (int mt = 0; mt < 4; mt++) {
                    float u0 = cf[mt][nt][0] + bA + dx0[mt] * wA;
                    float u1 = cf[mt][nt][1] + bB + dx0[mt] * wB;
                    float u2 = cf[mt][nt][2] + bA + dx1[mt] * wA;
                    float u3 = cf[mt][nt][3] + bB + dx1[mt] * wB;
                    if (u0 >= 0.9999f) sl0[mt] += wgt(u0);
                    if (u1 >= 0.9999f) sl0[mt] += wgt(u1);
                    if (u2 >= 0.9999f) sl1[mt] += wgt(u2);
                    if (u3 >= 0.9999f) sl1[mt] += wgt(u3);
                }
            }
        }

        #pragma unroll
        for (int mt = 0; mt < 4; mt++) {
            float s0 = sl0[mt], s1 = sl1[mt];
            s0 += __shfl_xor_sync(~0u, s0, 1); s0 += __shfl_xor_sync(~0u, s0, 2);
            s1 += __shfl_xor_sync(~0u, s1, 1); s1 += __shfl_xor_sync(~0u, s1, 2);
            if (qp == 0) {
                int r0 = wm * 64 + mt * 16 + g;
                if (s0 > 0.f) atomicAdd(&Ss[r0], s0);
                if (s1 > 0.f) atomicAdd(&Ss[r0 + 8], s1);
            }
        }
        __syncthreads();

        if (tid < 128 && Ss[tid] >= Slim) {
            int pos = atomicAdd(&g_nheavy, 1);
            g_heavy[pos] = R0 + tid;
        }

        // ---- certified light output (heavy rows overwritten by k_heavy)
        float4 z = make_float4(0.f, 0.f, 0.f, 0.f);
        #pragma unroll
        for (int it = 0; it < 32; it++) {
            int idx = it * 256 + tid;
            int row = idx >> 6, f = idx & 63;
            ((float4*)(out + (size_t)(R0 + row) * HID))[f] = z;
        }
        #pragma unroll
        for (int it = 0; it < 8; it++) {
            int idx = it * 256 + tid;
            int row = idx >> 4, f = idx & 15;
            float4 cv = make_float4(bcs[4 * f], bcs[4 * f + 1], bcs[4 * f + 2], bcs[4 * f + 3]);
            ((float4*)(out + (size_t)BATCH * HID + (size_t)(R0 + row) * COORD_DIM))[f] = cv;
        }
    }
}

// ---------------- heavy rows: exact fp32 recompute (coalesced) + simulation ----------------
__global__ void k_heavy(const float* __restrict__ spikes, const float* __restrict__ coords,
                        const float* __restrict__ b0, const float* __restrict__ b1,
                        const float* __restrict__ b_out, float* __restrict__ out) {
    int warps = (gridDim.x * blockDim.x) >> 5;
    int gw    = (blockIdx.x * blockDim.x + threadIdx.x) >> 5;
    int lane  = threadIdx.x & 31;
    int n     = g_nheavy;

    for (int idx = gw; idx < n; idx += warps) {
        int row = g_heavy[idx];
        float* actp = out + (size_t)row * HID;
        float* crdp = out + (size_t)BATCH * HID + (size_t)row * COORD_DIM;

        // exact fp32 c0 via transposed W0 (coalesced)
        const float* xs = spikes + (size_t)row * SPIKE_DIM;
        const float* xc = coords + (size_t)row * COORD_DIM;
        float s[8];
        #pragma unroll
        for (int r = 0; r < 8; r++) s[r] = 0.0f;
        #pragma unroll 4
        for (int k = 0; k < SPIKE_DIM; k++) {
            float xv = xs[k];
            const float* wr = g_W0T + (size_t)k * HID;
            #pragma unroll
            for (int r = 0; r < 8; r++) s[r] = fmaf(xv, wr[lane + 32 * r], s[r]);
        }
        #pragma unroll 4
        for (int k = 0; k < COORD_DIM; k++) {
            float xv = xc[k];
            const float* wr = g_W0T + (size_t)(SPIKE_DIM + k) * HID;
            #pragma unroll
            for (int r = 0; r < 8; r++) s[r] = fmaf(xv, wr[lane + 32 * r], s[r]);
        }

        float q[8], v0[8], v1[8], b1v[8];
        #pragma unroll
        for (int k = 0; k < 8; k++) {
            q[k] = OMB * (s[k] + b0[lane + 32 * k]);
            v0[k] = 0.0f; v1[k] = 0.0f;
            b1v[k] = b1[lane + 32 * k];
        }
        unsigned sp1m[8];
        #pragma unroll
        for (int k = 0; k < 8; k++) sp1m[k] = 0u;

        #pragma unroll 1
        for (int t = 0; t < NUM_STEPS; t++) {
            unsigned act[8];
            #pragma unroll
            for (int k = 0; k < 8; k++) {
                v0[k] = fmaf(BETA, v0[k], q[k]);
                bool sp = (v0[k] >= 1.0f);
                act[k] = __ballot_sync(~0u, sp);
                if (sp) v0[k] = 0.0f;
            }
            float c1[8];
            #pragma unroll
            for (int k = 0; k < 8; k++) c1[k] = b1v[k];
            #pragma unroll
            for (int k = 0; k < 8; k++) {
                unsigned m = act[k];
                while (m) {
                    int j = 32 * k + __ffs(m) - 1;
                    m &= m - 1;
                    const float* wr = g_W1T + (size_t)j * HID;
                    #pragma unroll
                    for (int r = 0; r < 8; r++) c1[r] += wr[lane + 32 * r];
                }
            }
            #pragma unroll
            for (int k = 0; k < 8; k++) {
                v1[k] = fmaf(BETA, v1[k], OMB * c1[k]);
                bool sp = (v1[k] >= 1.0f);
                unsigned b = __ballot_sync(~0u, sp);
                if (t == NUM_STEPS - 1) sp1m[k] = b;
                if (sp) v1[k] = 0.0f;
            }
        }

        #pragma unroll
        for (int k = 0; k < 8; k++)
            actp[lane + 32 * k] = ((sp1m[k] >> lane) & 1u) ? 1.0f : 0.0f;

        float ca = b_out[SPIKE_DIM + lane];
        float cb = b_out[SPIKE_DIM + 32 + lane];
        #pragma unroll
        for (int k = 0; k < 8; k++) {
            unsigned m = sp1m[k];
            while (m) {
                int i = 32 * k + __ffs(m) - 1;
                m &= m - 1;
                ca += g_WcT[(size_t)i * COORD_DIM + lane];
                cb += g_WcT[(size_t)i * COORD_DIM + 32 + lane];
            }
        }
        crdp[lane]      = ca;
        crdp[lane + 32] = cb;
    }
}

// ---------------- launch ----------------
extern "C" void kernel_launch(void* const* d_in, const int* in_sizes, int n_in,
                              void* d_out, int out_size) {
    const float* spikes = (const float*)d_in[0];
    const float* coords = (const float*)d_in[1];
    const float* W0     = (const float*)d_in[2];
    const float* b0     = (const float*)d_in[3];
    const float* W1     = (const float*)d_in[4];
    const float* b1     = (const float*)d_in[5];
    const float* W_out  = (const float*)d_in[6];
    const float* b_out  = (const float*)d_in[7];
    float* out = (float*)d_out;

    k_prep<<<256, 256>>>(W0, W1, b1, W_out);

    cudaFuncSetAttribute(k_gemm, cudaFuncAttributeMaxDynamicSharedMemorySize, GEMM_SMEM);
    k_gemm<<<148, 256, GEMM_SMEM>>>(spikes, coords, b0, b_out, out);

    k_heavy<<<256, 256>>>(spikes, coords, b0, b1, b_out, out);
}

// round 7
// speedup vs baseline: 2.5904x; 1.2103x over previous
#include <cuda_runtime.h>
#include <cuda_bf16.h>
#include <cstdint>

#define BATCH      131072
#define HID        256
#define SPIKE_DIM  128
#define COORD_DIM  64
#define IN_DIM     192
#define NUM_STEPS  25
#define BETA       0.7f
#define OMB        (1.0f - BETA)

#define TILES      (BATCH / 128)   // 1024
#define NBLK       148
#define XP         100             // u32 stride per X row (96 used; 100%32==4 -> LDSM conflict-free)
#define WP         100
#define DELTA      0.004f          // rigorous bf16 Cauchy-Schwarz error coefficient

// ---------------- device scratch ----------------
__device__ unsigned g_W0b2[HID * WP];          // W0 bf16x2, [j][k2], padded stride
__device__ float    g_W0T[IN_DIM * HID];       // W0T[k][j] = W0[j][k]  (coalesced heavy path)
__device__ float    g_wn[HID];                 // ||W0 row j||_2
__device__ float    g_W1T[HID * HID];          // W1T[j][i] = W1[i][j]
__device__ float    g_WcT[HID * COORD_DIM];    // WcT[i][m] = W_out[128+m][i]
__device__ unsigned g_wmax_u, g_bmax_u;        // monotone max (replay-safe)
__device__ int      g_heavy[BATCH];
__device__ int      g_nheavy;

// ---------------- helpers ----------------
__device__ __forceinline__ uint32_t smem_u32(const void* p) {
    uint32_t a;
    asm("{ .reg .u64 t; cvta.to.shared.u64 t, %1; cvt.u32.u64 %0, t; }" : "=r"(a) : "l"(p));
    return a;
}
__device__ __forceinline__ unsigned pk(float lo, float hi) {
    __nv_bfloat162 h;
    h.x = __float2bfloat16_rn(lo);
    h.y = __float2bfloat16_rn(hi);
    return *reinterpret_cast<unsigned*>(&h);
}
__device__ __forceinline__ void mma16816(float c[4], const unsigned a[4], const unsigned b[2]) {
    asm volatile(
        "mma.sync.aligned.m16n8k16.row.col.f32.bf16.bf16.f32 "
        "{%0,%1,%2,%3}, {%4,%5,%6,%7}, {%8,%9}, {%0,%1,%2,%3};"
        : "+f"(c[0]), "+f"(c[1]), "+f"(c[2]), "+f"(c[3])
        : "r"(a[0]), "r"(a[1]), "r"(a[2]), "r"(a[3]), "r"(b[0]), "r"(b[1]));
}
__device__ __forceinline__ void ldsm4(uint32_t r[4], uint32_t addr) {
    asm volatile("ldmatrix.sync.aligned.m8n8.x4.shared.b16 {%0,%1,%2,%3}, [%4];"
        : "=r"(r[0]), "=r"(r[1]), "=r"(r[2]), "=r"(r[3]) : "r"(addr));
}
// rigorous spike-rate weight: upper-bounds geometric-sum contribution for drive <= c
__device__ __forceinline__ float wgt(float c) {
    float d = fmaxf(1.0f - 0.3f * c, 0.2101f);
    return fminf(__fdividef(0.70007f * c, d), 3.3334f);
}

// ---------------- fused prep ----------------
__global__ void k_prep(const float* __restrict__ W0, const float* __restrict__ W1,
                       const float* __restrict__ b1, const float* __restrict__ W_out) {
    int i = blockIdx.x, j = threadIdx.x;
    if (i == 0 && j == 0) g_nheavy = 0;

    float v = W1[i * HID + j];
    g_W1T[j * HID + i] = v;

    float m = fabsf(v);
    #pragma unroll
    for (int off = 16; off; off >>= 1) m = fmaxf(m, __shfl_xor_sync(~0u, m, off));
    __shared__ float sm[8];
    __shared__ float r3[3];
    if ((j & 31) == 0) sm[j >> 5] = m;

    if (j < 96) {
        float a = W0[i * IN_DIM + 2 * j], b = W0[i * IN_DIM + 2 * j + 1];
        g_W0b2[i * WP + j] = pk(a, b);
        g_W0T[(2 * j) * HID + i]     = a;
        g_W0T[(2 * j + 1) * HID + i] = b;
        float sq = fmaf(a, a, b * b);
        #pragma unroll
        for (int o = 16; o; o >>= 1) sq += __shfl_xor_sync(~0u, sq, o);
        if ((j & 31) == 0) r3[j >> 5] = sq;
    }
    __syncthreads();
    if (j < 8) {
        float t = sm[j];
        #pragma unroll
        for (int off = 4; off; off >>= 1) t = fmaxf(t, __shfl_xor_sync(0xffu, t, off));
        if (j == 0) atomicMax(&g_wmax_u, __float_as_uint(t));
    }
    if (i == 0) atomicMax(&g_bmax_u, __float_as_uint(fabsf(b1[j])));
    if (j == 0) g_wn[i] = sqrtf(r3[0] + r3[1] + r3[2]);
    if (i < COORD_DIM) g_WcT[j * COORD_DIM + i] = W_out[(SPIKE_DIM + i) * HID + j];
}

// ---------------- GEMM: 512 threads, double-buffered X, pipelined ----------------
#define U_WS  0
#define U_X0  25600
#define U_X1  38400
#define U_B0  51200
#define U_WN  51456
#define U_BC  51712
#define U_XN  51776          // [2][128]
#define U_SS  52032          // [128]
#define GEMM_SMEM (52160 * 4)

__global__ __launch_bounds__(512, 1)
void k_gemm(const float* __restrict__ spikes, const float* __restrict__ coords,
            const float* __restrict__ b0, const float* __restrict__ b_out,
            float* __restrict__ out) {
    extern __shared__ unsigned sh[];
    unsigned* Ws  = sh + U_WS;
    float*    b0s = (float*)(sh + U_B0);
    float*    wns = (float*)(sh + U_WN);
    float*    bcs = (float*)(sh + U_BC);
    float*    xn2 = (float*)(sh + U_XN);   // [2][128]
    float*    Ss  = (float*)(sh + U_SS);   // [128]

    int tid  = threadIdx.x;
    int lane = tid & 31;
    int wid  = tid >> 5;
    int g    = lane >> 2, qp = lane & 3;
    int wm   = wid >> 2,  wn_ = wid & 3;   // wm: M-quarter (32 rows), wn_: 64-col block

    // one-time fills
    {
        const float4* src = (const float4*)g_W0b2;
        float4* dst = (float4*)Ws;
        #pragma unroll
        for (int i = 0; i < 13; i++) {
            int idx = i * 512 + tid;
            if (idx < 6400) dst[idx] = src[idx];
        }
        if (tid < 256) { b0s[tid] = b0[tid]; wns[tid] = g_wn[tid]; }
        if (tid < 64)  bcs[tid] = b_out[SPIKE_DIM + tid];
        if (tid < 128) { Ss[tid] = 0.0f; xn2[tid] = 0.0f; }
    }

    float Slim;
    {
        float wmax = __uint_as_float(g_wmax_u);
        float bmax = __uint_as_float(g_bmax_u);
        if (bmax >= 0.999f)    Slim = -1.0f;
        else if (wmax <= 0.0f) Slim = 1e30f;
        else Slim = __fdividef(0.999f - bmax, 0.3000001f * wmax) * 0.998f - 0.01f;
    }

    uint32_t xs_b[2] = { smem_u32(sh + U_X0), smem_u32(sh + U_X1) };
    uint32_t ws_b    = smem_u32(Ws);
    uint32_t a_off   = (uint32_t)(((wm * 32 + (lane & 15)) * XP + ((lane >> 4) << 2)) * 4);
    uint32_t b_base  = ws_b + (uint32_t)((((lane >> 4) * 8 + (lane & 7)) * WP + (((lane >> 3) & 1) << 2)) * 4);

    __syncthreads();

    // ---- prologue: load tile blockIdx.x into buffer 0
    {
        int R0 = blockIdx.x * 128;
        unsigned* Xs = sh + U_X0;
        #pragma unroll
        for (int it = 0; it < 12; it++) {
            int idx = it * 512 + tid;
            int row = idx / 48, f4 = idx % 48;
            float4 v;
            if (f4 < 32) v = ((const float4*)(spikes + (size_t)(R0 + row) * SPIKE_DIM))[f4];
            else         v = ((const float4*)(coords + (size_t)(R0 + row) * COORD_DIM))[f4 - 32];
            *(uint2*)(Xs + row * XP + 2 * f4) = make_uint2(pk(v.x, v.y), pk(v.z, v.w));
            float sq = fmaf(v.x, v.x, fmaf(v.y, v.y, fmaf(v.z, v.z, v.w * v.w)));
            #pragma unroll
            for (int o = 8; o; o >>= 1) sq += __shfl_xor_sync(~0u, sq, o);
            if ((lane & 15) == 0) atomicAdd(&xn2[row], sq);
        }
    }
    __syncthreads();

    int cur = 0;
    #pragma unroll 1
    for (int t = blockIdx.x; t < TILES; t += NBLK) {
        int R0 = t * 128;

        // ---- light output stores (independent of MMA; overlap memory with compute)
        float4 z = make_float4(0.f, 0.f, 0.f, 0.f);
        #pragma unroll
        for (int it = 0; it < 16; it++) {
            int idx = it * 512 + tid;
            int row = idx >> 6, f = idx & 63;
            ((float4*)(out + (size_t)(R0 + row) * HID))[f] = z;
        }
        #pragma unroll
        for (int it = 0; it < 4; it++) {
            int idx = it * 512 + tid;
            int row = idx >> 4, f = idx & 15;
            float4 cv = make_float4(bcs[4 * f], bcs[4 * f + 1], bcs[4 * f + 2], bcs[4 * f + 3]);
            ((float4*)(out + (size_t)BATCH * HID + (size_t)(R0 + row) * COORD_DIM))[f] = cv;
        }

        // ---- MMA + classify
        uint32_t a_base = xs_b[cur] + a_off;
        const float* xn = xn2 + cur * 128;
        float dx0[2], dx1[2];
        #pragma unroll
        for (int mt = 0; mt < 2; mt++) {
            int r0 = wm * 32 + mt * 16 + g;
            dx0[mt] = DELTA * sqrtf(xn[r0]);
            dx1[mt] = DELTA * sqrtf(xn[r0 + 8]);
        }
        float sl0[2] = {0.f, 0.f}, sl1[2] = {0.f, 0.f};

        #pragma unroll
        for (int h = 0; h < 2; h++) {
            float cf[2][4][4];
            #pragma unroll
            for (int mt = 0; mt < 2; mt++)
                #pragma unroll
                for (int nt = 0; nt < 4; nt++)
                    #pragma unroll
                    for (int q = 0; q < 4; q++) cf[mt][nt][q] = 0.0f;

            #pragma unroll
            for (int kk = 0; kk < 12; kk++) {
                uint32_t a[2][4], bfr[2][4];
                #pragma unroll
                for (int mt = 0; mt < 2; mt++)
                    ldsm4(a[mt], a_base + (unsigned)((mt * 16 * XP + kk * 8) * 4));
                #pragma unroll
                for (int np = 0; np < 2; np++)
                    ldsm4(bfr[np], b_base + (unsigned)((((wn_ * 64 + h * 32 + np * 16) * WP) + kk * 8) * 4));
                #pragma unroll
                for (int mt = 0; mt < 2; mt++)
                    #pragma unroll
                    for (int nt = 0; nt < 4; nt++)
                        mma16816(cf[mt][nt], a[mt], &bfr[nt >> 1][(nt & 1) * 2]);
            }

            #pragma unroll
            for (int nt = 0; nt < 4; nt++) {
                int c = wn_ * 64 + h * 32 + nt * 8 + 2 * qp;
                float bA = b0s[c], bB = b0s[c + 1];
                float wA = wns[c], wB = wns[c + 1];
                #pragma unroll
                for (int mt = 0; mt < 2; mt++) {
                    float u0 = cf[mt][nt][0] + bA + dx0[mt] * wA;
                    float u1 = cf[mt][nt][1] + bB + dx0[mt] * wB;
                    float u2 = cf[mt][nt][2] + bA + dx1[mt] * wA;
                    float u3 = cf[mt][nt][3] + bB + dx1[mt] * wB;
                    if (u0 >= 0.9999f) sl0[mt] += wgt(u0);
                    if (u1 >= 0.9999f) sl0[mt] += wgt(u1);
                    if (u2 >= 0.9999f) sl1[mt] += wgt(u2);
                    if (u3 >= 0.9999f) sl1[mt] += wgt(u3);
                }
            }
        }

        #pragma unroll
        for (int mt = 0; mt < 2; mt++) {
            float s0 = sl0[mt], s1 = sl1[mt];
            s0 += __shfl_xor_sync(~0u, s0, 1); s0 += __shfl_xor_sync(~0u, s0, 2);
            s1 += __shfl_xor_sync(~0u, s1, 1); s1 += __shfl_xor_sync(~0u, s1, 2);
            if (qp == 0) {
                int r0 = wm * 32 + mt * 16 + g;
                if (s0 > 0.f) atomicAdd(&Ss[r0], s0);
                if (s1 > 0.f) atomicAdd(&Ss[r0 + 8], s1);
            }
        }
        __syncthreads();

        // ---- flags; reset Ss and next xn2 bank
        if (tid < 128) {
            if (Ss[tid] >= Slim) {
                int pos = atomicAdd(&g_nheavy, 1);
                g_heavy[pos] = R0 + tid;
            }
            Ss[tid] = 0.0f;
            xn2[(cur ^ 1) * 128 + tid] = 0.0f;
        }
        __syncthreads();

        // ---- prefetch next tile into other buffer
        int tn = t + NBLK;
        if (tn < TILES) {
            int Rn = tn * 128;
            unsigned* Xs = sh + (cur ? U_X0 : U_X1);
            float* xnn = xn2 + (cur ^ 1) * 128;
            #pragma unroll
            for (int it = 0; it < 12; it++) {
                int idx = it * 512 + tid;
                int row = idx / 48, f4 = idx % 48;
                float4 v;
                if (f4 < 32) v = ((const float4*)(spikes + (size_t)(Rn + row) * SPIKE_DIM))[f4];
                else         v = ((const float4*)(coords + (size_t)(Rn + row) * COORD_DIM))[f4 - 32];
                *(uint2*)(Xs + row * XP + 2 * f4) = make_uint2(pk(v.x, v.y), pk(v.z, v.w));
                float sq = fmaf(v.x, v.x, fmaf(v.y, v.y, fmaf(v.z, v.z, v.w * v.w)));
                #pragma unroll
                for (int o = 8; o; o >>= 1) sq += __shfl_xor_sync(~0u, sq, o);
                if ((lane & 15) == 0) atomicAdd(&xnn[row], sq);
            }
        }
        __syncthreads();
        cur ^= 1;
    }
}

// ---------------- heavy rows: exact fp32 recompute (coalesced) + simulation ----------------
__global__ void k_heavy(const float* __restrict__ spikes, const float* __restrict__ coords,
                        const float* __restrict__ b0, const float* __restrict__ b1,
                        const float* __restrict__ b_out, float* __restrict__ out) {
    int warps = (gridDim.x * blockDim.x) >> 5;
    int gw    = (blockIdx.x * blockDim.x + threadIdx.x) >> 5;
    int lane  = threadIdx.x & 31;
    int n     = g_nheavy;

    for (int idx = gw; idx < n; idx += warps) {
        int row = g_heavy[idx];
        float* actp = out + (size_t)row * HID;
        float* crdp = out + (size_t)BATCH * HID + (size_t)row * COORD_DIM;

        const float* xs = spikes + (size_t)row * SPIKE_DIM;
        const float* xc = coords + (size_t)row * COORD_DIM;
        float s[8];
        #pragma unroll
        for (int r = 0; r < 8; r++) s[r] = 0.0f;
        #pragma unroll 4
        for (int k = 0; k < SPIKE_DIM; k++) {
            float xv = xs[k];
            const float* wr = g_W0T + (size_t)k * HID;
            #pragma unroll
            for (int r = 0; r < 8; r++) s[r] = fmaf(xv, wr[lane + 32 * r], s[r]);
        }
        #pragma unroll 4
        for (int k = 0; k < COORD_DIM; k++) {
            float xv = xc[k];
            const float* wr = g_W0T + (size_t)(SPIKE_DIM + k) * HID;
            #pragma unroll
            for (int r = 0; r < 8; r++) s[r] = fmaf(xv, wr[lane + 32 * r], s[r]);
        }

        float q[8], v0[8], v1[8], b1v[8];
        #pragma unroll
        for (int k = 0; k < 8; k++) {
            q[k] = OMB * (s[k] + b0[lane + 32 * k]);
            v0[k] = 0.0f; v1[k] = 0.0f;
            b1v[k] = b1[lane + 32 * k];
        }
        unsigned sp1m[8];
        #pragma unroll
        for (int k = 0; k < 8; k++) sp1m[k] = 0u;

        #pragma unroll 1
        for (int t = 0; t < NUM_STEPS; t++) {
            unsigned act[8];
            #pragma unroll
            for (int k = 0; k < 8; k++) {
                v0[k] = fmaf(BETA, v0[k], q[k]);
                bool sp = (v0[k] >= 1.0f);
                act[k] = __ballot_sync(~0u, sp);
                if (sp) v0[k] = 0.0f;
            }
            float c1[8];
            #pragma unroll
            for (int k = 0; k < 8; k++) c1[k] = b1v[k];
            #pragma unroll
            for (int k = 0; k < 8; k++) {
                unsigned m = act[k];
                while (m) {
                    int j = 32 * k + __ffs(m) - 1;
                    m &= m - 1;
                    const float* wr = g_W1T + (size_t)j * HID;
                    #pragma unroll
                    for (int r = 0; r < 8; r++) c1[r] += wr[lane + 32 * r];
                }
            }
            #pragma unroll
            for (int k = 0; k < 8; k++) {
                v1[k] = fmaf(BETA, v1[k], OMB * c1[k]);
                bool sp = (v1[k] >= 1.0f);
                unsigned b = __ballot_sync(~0u, sp);
                if (t == NUM_STEPS - 1) sp1m[k] = b;
                if (sp) v1[k] = 0.0f;
            }
        }

        #pragma unroll
        for (int k = 0; k < 8; k++)
            actp[lane + 32 * k] = ((sp1m[k] >> lane) & 1u) ? 1.0f : 0.0f;

        float ca = b_out[SPIKE_DIM + lane];
        float cb = b_out[SPIKE_DIM + 32 + lane];
        #pragma unroll
        for (int k = 0; k < 8; k++) {
            unsigned m = sp1m[k];
            while (m) {
                int i = 32 * k + __ffs(m) - 1;
                m &= m - 1;
                ca += g_WcT[(size_t)i * COORD_DIM + lane];
                cb += g_WcT[(size_t)i * COORD_DIM + 32 + lane];
            }
        }
        crdp[lane]      = ca;
        crdp[lane + 32] = cb;
    }
}

// ---------------- launch ----------------
extern "C" void kernel_launch(void* const* d_in, const int* in_sizes, int n_in,
                              void* d_out, int out_size) {
    const float* spikes = (const float*)d_in[0];
    const float* coords = (const float*)d_in[1];
    const float* W0     = (const float*)d_in[2];
    const float* b0     = (const float*)d_in[3];
    const float* W1     = (const float*)d_in[4];
    const float* b1     = (const float*)d_in[5];
    const float* W_out  = (const float*)d_in[6];
    const float* b_out  = (const float*)d_in[7];
    float* out = (float*)d_out;

    k_prep<<<256, 256>>>(W0, W1, b1, W_out);

    cudaFuncSetAttribute(k_gemm, cudaFuncAttributeMaxDynamicSharedMemorySize, GEMM_SMEM);
    k_gemm<<<NBLK, 512, GEMM_SMEM>>>(spikes, coords, b0, b_out, out);

    k_heavy<<<256, 256>>>(spikes, coords, b0, b1, b_out, out);
}

// round 8
// speedup vs baseline: 2.7694x; 1.0691x over previous
#include <cuda_runtime.h>
#include <cuda_bf16.h>
#include <cstdint>

#define BATCH      131072
#define HID        256
#define SPIKE_DIM  128
#define COORD_DIM  64
#define IN_DIM     192
#define NUM_STEPS  25
#define BETA       0.7f
#define OMB        (1.0f - BETA)

#define TILES      (BATCH / 128)   // 1024
#define NBLK       148
#define XP         100             // u32 stride per X row (96 used; 100%32==4 -> LDSM conflict-free)
#define WP         100
#define DELTA      0.004f          // rigorous bf16 Cauchy-Schwarz error coefficient

// ---------------- device scratch ----------------
__device__ unsigned g_W0b2[HID * WP];          // W0 bf16x2, [j][k2], padded stride
__device__ float    g_W0T[IN_DIM * HID];       // W0T[k][j] = W0[j][k]  (coalesced heavy path)
__device__ float    g_wn[HID];                 // ||W0 row j||_2
__device__ float    g_W1T[HID * HID];          // W1T[j][i] = W1[i][j]
__device__ float    g_WcT[HID * COORD_DIM];    // WcT[i][m] = W_out[128+m][i]
__device__ unsigned g_wmax_u, g_bmax_u;        // monotone max (replay-safe)
__device__ int      g_heavy[BATCH];
__device__ int      g_nheavy;

// ---------------- helpers ----------------
__device__ __forceinline__ uint32_t smem_u32(const void* p) {
    uint32_t a;
    asm("{ .reg .u64 t; cvta.to.shared.u64 t, %1; cvt.u32.u64 %0, t; }" : "=r"(a) : "l"(p));
    return a;
}
__device__ __forceinline__ unsigned pk(float lo, float hi) {
    __nv_bfloat162 h;
    h.x = __float2bfloat16_rn(lo);
    h.y = __float2bfloat16_rn(hi);
    return *reinterpret_cast<unsigned*>(&h);
}
__device__ __forceinline__ void mma16816(float c[4], const unsigned a[4], const unsigned b[2]) {
    asm volatile(
        "mma.sync.aligned.m16n8k16.row.col.f32.bf16.bf16.f32 "
        "{%0,%1,%2,%3}, {%4,%5,%6,%7}, {%8,%9}, {%0,%1,%2,%3};"
        : "+f"(c[0]), "+f"(c[1]), "+f"(c[2]), "+f"(c[3])
        : "r"(a[0]), "r"(a[1]), "r"(a[2]), "r"(a[3]), "r"(b[0]), "r"(b[1]));
}
__device__ __forceinline__ void ldsm4(uint32_t r[4], uint32_t addr) {
    asm volatile("ldmatrix.sync.aligned.m8n8.x4.shared.b16 {%0,%1,%2,%3}, [%4];"
        : "=r"(r[0]), "=r"(r[1]), "=r"(r[2]), "=r"(r[3]) : "r"(addr));
}
// rigorous spike-rate weight: upper-bounds geometric-sum contribution for drive <= c
__device__ __forceinline__ float wgt(float c) {
    float d = fmaxf(1.0f - 0.3f * c, 0.2101f);
    return fminf(__fdividef(0.70007f * c, d), 3.3334f);
}

// ---------------- fused prep ----------------
__global__ void k_prep(const float* __restrict__ W0, const float* __restrict__ W1,
                       const float* __restrict__ b1, const float* __restrict__ W_out) {
    int i = blockIdx.x, j = threadIdx.x;
    if (i == 0 && j == 0) g_nheavy = 0;

    float v = W1[i * HID + j];
    g_W1T[j * HID + i] = v;

    float m = fabsf(v);
    #pragma unroll
    for (int off = 16; off; off >>= 1) m = fmaxf(m, __shfl_xor_sync(~0u, m, off));
    __shared__ float sm[8];
    __shared__ float r3[3];
    if ((j & 31) == 0) sm[j >> 5] = m;

    if (j < 96) {
        float a = W0[i * IN_DIM + 2 * j], b = W0[i * IN_DIM + 2 * j + 1];
        g_W0b2[i * WP + j] = pk(a, b);
        g_W0T[(2 * j) * HID + i]     = a;
        g_W0T[(2 * j + 1) * HID + i] = b;
        float sq = fmaf(a, a, b * b);
        #pragma unroll
        for (int o = 16; o; o >>= 1) sq += __shfl_xor_sync(~0u, sq, o);
        if ((j & 31) == 0) r3[j >> 5] = sq;
    }
    __syncthreads();
    if (j < 8) {
        float t = sm[j];
        #pragma unroll
        for (int off = 4; off; off >>= 1) t = fmaxf(t, __shfl_xor_sync(0xffu, t, off));
        if (j == 0) atomicMax(&g_wmax_u, __float_as_uint(t));
    }
    if (i == 0) atomicMax(&g_bmax_u, __float_as_uint(fabsf(b1[j])));
    if (j == 0) g_wn[i] = sqrtf(r3[0] + r3[1] + r3[2]);
    if (i < COORD_DIM) g_WcT[j * COORD_DIM + i] = W_out[(SPIKE_DIM + i) * HID + j];
}

// ---------------- GEMM: 512 threads, double-buffered X, register-pipelined loads ----------------
#define U_WS  0
#define U_X0  25600
#define U_X1  38400
#define U_B0  51200
#define U_WN  51456
#define U_BC  51712
#define U_XN  51776          // [2][128]
#define U_SS  52032          // [128]
#define GEMM_SMEM (52160 * 4)

__global__ __launch_bounds__(512, 1)
void k_gemm(const float* __restrict__ spikes, const float* __restrict__ coords,
            const float* __restrict__ b0, const float* __restrict__ b_out,
            float* __restrict__ out) {
    extern __shared__ unsigned sh[];
    unsigned* Ws  = sh + U_WS;
    float*    b0s = (float*)(sh + U_B0);
    float*    wns = (float*)(sh + U_WN);
    float*    bcs = (float*)(sh + U_BC);
    float*    xn2 = (float*)(sh + U_XN);   // [2][128]
    float*    Ss  = (float*)(sh + U_SS);   // [128]

    int tid  = threadIdx.x;
    int lane = tid & 31;
    int wid  = tid >> 5;
    int g    = lane >> 2, qp = lane & 3;
    int wm   = wid >> 2,  wn_ = wid & 3;

    // one-time fills
    {
        const float4* src = (const float4*)g_W0b2;
        float4* dst = (float4*)Ws;
        #pragma unroll
        for (int i = 0; i < 13; i++) {
            int idx = i * 512 + tid;
            if (idx < 6400) dst[idx] = src[idx];
        }
        if (tid < 256) { b0s[tid] = b0[tid]; wns[tid] = g_wn[tid]; xn2[tid] = 0.0f; }
        if (tid < 64)  bcs[tid] = b_out[SPIKE_DIM + tid];
        if (tid < 128) Ss[tid] = 0.0f;
    }

    float Slim;
    {
        float wmax = __uint_as_float(g_wmax_u);
        float bmax = __uint_as_float(g_bmax_u);
        if (bmax >= 0.999f)    Slim = -1.0f;
        else if (wmax <= 0.0f) Slim = 1e30f;
        else Slim = __fdividef(0.999f - bmax, 0.3000001f * wmax) * 0.998f - 0.01f;
    }

    uint32_t xs_b[2] = { smem_u32(sh + U_X0), smem_u32(sh + U_X1) };
    uint32_t ws_b    = smem_u32(Ws);
    uint32_t a_off   = (uint32_t)(((wm * 32 + (lane & 15)) * XP + ((lane >> 4) << 2)) * 4);
    uint32_t b_base  = ws_b + (uint32_t)((((lane >> 4) * 8 + (lane & 7)) * WP + (((lane >> 3) & 1) << 2)) * 4);

    __syncthreads();

    // ---- prologue: load tile blockIdx.x into buffer 0 (accumulates xn2 bank 0)
    {
        int R0 = blockIdx.x * 128;
        unsigned* Xs = sh + U_X0;
        #pragma unroll
        for (int it = 0; it < 12; it++) {
            int idx = it * 512 + tid;
            int row = idx / 48, f4 = idx % 48;
            float4 v;
            if (f4 < 32) v = ((const float4*)(spikes + (size_t)(R0 + row) * SPIKE_DIM))[f4];
            else         v = ((const float4*)(coords + (size_t)(R0 + row) * COORD_DIM))[f4 - 32];
            *(uint2*)(Xs + row * XP + 2 * f4) = make_uint2(pk(v.x, v.y), pk(v.z, v.w));
            float sq = fmaf(v.x, v.x, fmaf(v.y, v.y, fmaf(v.z, v.z, v.w * v.w)));
            #pragma unroll
            for (int o = 8; o; o >>= 1) sq += __shfl_xor_sync(~0u, sq, o);
            if ((lane & 15) == 0) atomicAdd(&xn2[row], sq);
        }
    }
    __syncthreads();

    int cur = 0;
    #pragma unroll 1
    for (int t = blockIdx.x; t < TILES; t += NBLK) {
        int R0 = t * 128;
        int tn = t + NBLK;
        bool hn = (tn < TILES);
        int Rn = tn * 128;
        unsigned* Xn  = sh + (cur ? U_X0 : U_X1);
        float*    xnn = xn2 + (cur ^ 1) * 128;

        // ---- issue LDG half 0 for tile t+NBLK (latency hidden under MMA h=0)
        float4 pf[6];
        if (hn) {
            #pragma unroll
            for (int it = 0; it < 6; it++) {
                int idx = it * 512 + tid;
                int row = idx / 48, f4 = idx % 48;
                if (f4 < 32) pf[it] = __ldg((const float4*)(spikes + (size_t)(Rn + row) * SPIKE_DIM) + f4);
                else         pf[it] = __ldg((const float4*)(coords + (size_t)(Rn + row) * COORD_DIM) + (f4 - 32));
            }
        }

        // ---- light output stores (independent; overlap with MMA)
        float4 z = make_float4(0.f, 0.f, 0.f, 0.f);
        #pragma unroll
        for (int it = 0; it < 16; it++) {
            int idx = it * 512 + tid;
            int row = idx >> 6, f = idx & 63;
            ((float4*)(out + (size_t)(R0 + row) * HID))[f] = z;
        }
        #pragma unroll
        for (int it = 0; it < 4; it++) {
            int idx = it * 512 + tid;
            int row = idx >> 4, f = idx & 15;
            float4 cv = make_float4(bcs[4 * f], bcs[4 * f + 1], bcs[4 * f + 2], bcs[4 * f + 3]);
            ((float4*)(out + (size_t)BATCH * HID + (size_t)(R0 + row) * COORD_DIM))[f] = cv;
        }

        uint32_t a_base = xs_b[cur] + a_off;
        const float* xn = xn2 + cur * 128;
        float dx0[2], dx1[2];
        #pragma unroll
        for (int mt = 0; mt < 2; mt++) {
            int r0 = wm * 32 + mt * 16 + g;
            dx0[mt] = DELTA * sqrtf(xn[r0]);
            dx1[mt] = DELTA * sqrtf(xn[r0 + 8]);
        }
        float sl0[2] = {0.f, 0.f}, sl1[2] = {0.f, 0.f};

        #pragma unroll 1
        for (int h = 0; h < 2; h++) {
            float cf[2][4][4];
            #pragma unroll
            for (int mt = 0; mt < 2; mt++)
                #pragma unroll
                for (int nt = 0; nt < 4; nt++)
                    #pragma unroll
                    for (int q = 0; q < 4; q++) cf[mt][nt][q] = 0.0f;

            #pragma unroll
            for (int kk = 0; kk < 12; kk++) {
                uint32_t a[2][4], bfr[2][4];
                #pragma unroll
                for (int mt = 0; mt < 2; mt++)
                    ldsm4(a[mt], a_base + (unsigned)((mt * 16 * XP + kk * 8) * 4));
                #pragma unroll
                for (int np = 0; np < 2; np++)
                    ldsm4(bfr[np], b_base + (unsigned)((((wn_ * 64 + h * 32 + np * 16) * WP) + kk * 8) * 4));
                #pragma unroll
                for (int mt = 0; mt < 2; mt++)
                    #pragma unroll
                    for (int nt = 0; nt < 4; nt++)
                        mma16816(cf[mt][nt], a[mt], &bfr[nt >> 1][(nt & 1) * 2]);
            }

            #pragma unroll
            for (int nt = 0; nt < 4; nt++) {
                int c = wn_ * 64 + h * 32 + nt * 8 + 2 * qp;
                float bA = b0s[c], bB = b0s[c + 1];
                float wA = wns[c], wB = wns[c + 1];
                #pragma unroll
                for (int mt = 0; mt < 2; mt++) {
                    float u0 = cf[mt][nt][0] + bA + dx0[mt] * wA;
                    float u1 = cf[mt][nt][1] + bB + dx0[mt] * wB;
                    float u2 = cf[mt][nt][2] + bA + dx1[mt] * wA;
                    float u3 = cf[mt][nt][3] + bB + dx1[mt] * wB;
                    if (u0 >= 0.9999f) sl0[mt] += wgt(u0);
                    if (u1 >= 0.9999f) sl0[mt] += wgt(u1);
                    if (u2 >= 0.9999f) sl1[mt] += wgt(u2);
                    if (u3 >= 0.9999f) sl1[mt] += wgt(u3);
                }
            }

            // ---- between/after MMA halves: convert arrived LDGs, issue next half
            if (hn) {
                int base_it = h * 6;
                #pragma unroll
                for (int it = 0; it < 6; it++) {
                    int idx = (base_it + it) * 512 + tid;
                    int row = idx / 48, f4 = idx % 48;
                    float4 v = pf[it];
                    *(uint2*)(Xn + row * XP + 2 * f4) = make_uint2(pk(v.x, v.y), pk(v.z, v.w));
                    float sq = fmaf(v.x, v.x, fmaf(v.y, v.y, fmaf(v.z, v.z, v.w * v.w)));
                    #pragma unroll
                    for (int o = 8; o; o >>= 1) sq += __shfl_xor_sync(~0u, sq, o);
                    if ((lane & 15) == 0) atomicAdd(&xnn[row], sq);
                }
                if (h == 0) {
                    #pragma unroll
                    for (int it = 6; it < 12; it++) {
                        int idx = it * 512 + tid;
                        int row = idx / 48, f4 = idx % 48;
                        if (f4 < 32) pf[it - 6] = __ldg((const float4*)(spikes + (size_t)(Rn + row) * SPIKE_DIM) + f4);
                        else         pf[it - 6] = __ldg((const float4*)(coords + (size_t)(Rn + row) * COORD_DIM) + (f4 - 32));
                    }
                }
            }
        }

        #pragma unroll
        for (int mt = 0; mt < 2; mt++) {
            float s0 = sl0[mt], s1 = sl1[mt];
            s0 += __shfl_xor_sync(~0u, s0, 1); s0 += __shfl_xor_sync(~0u, s0, 2);
            s1 += __shfl_xor_sync(~0u, s1, 1); s1 += __shfl_xor_sync(~0u, s1, 2);
            if (qp == 0) {
                int r0 = wm * 32 + mt * 16 + g;
                if (s0 > 0.f) atomicAdd(&Ss[r0], s0);
                if (s1 > 0.f) atomicAdd(&Ss[r0 + 8], s1);
            }
        }
        __syncthreads();

        // ---- flags; reset Ss and the just-consumed xn2 bank (reused at t+2)
        if (tid < 128) {
            if (Ss[tid] >= Slim) {
                int pos = atomicAdd(&g_nheavy, 1);
                g_heavy[pos] = R0 + tid;
            }
            Ss[tid] = 0.0f;
            xn2[cur * 128 + tid] = 0.0f;
        }
        __syncthreads();
        cur ^= 1;
    }
}

// ---------------- heavy rows: exact fp32 recompute (coalesced) + simulation ----------------
__global__ void k_heavy(const float* __restrict__ spikes, const float* __restrict__ coords,
                        const float* __restrict__ b0, const float* __restrict__ b1,
                        const float* __restrict__ b_out, float* __restrict__ out) {
    int warps = (gridDim.x * blockDim.x) >> 5;
    int gw    = (blockIdx.x * blockDim.x + threadIdx.x) >> 5;
    int lane  = threadIdx.x & 31;
    int n     = g_nheavy;

    for (int idx = gw; idx < n; idx += warps) {
        int row = g_heavy[idx];
        float* actp = out + (size_t)row * HID;
        float* crdp = out + (size_t)BATCH * HID + (size_t)row * COORD_DIM;

        const float* xs = spikes + (size_t)row * SPIKE_DIM;
        const float* xc = coords + (size_t)row * COORD_DIM;
        float s[8];
        #pragma unroll
        for (int r = 0; r < 8; r++) s[r] = 0.0f;
        #pragma unroll 4
        for (int k = 0; k < SPIKE_DIM; k++) {
            float xv = xs[k];
            const float* wr = g_W0T + (size_t)k * HID;
            #pragma unroll
            for (int r = 0; r < 8; r++) s[r] = fmaf(xv, wr[lane + 32 * r], s[r]);
        }
        #pragma unroll 4
        for (int k = 0; k < COORD_DIM; k++) {
            float xv = xc[k];
            const float* wr = g_W0T + (size_t)(SPIKE_DIM + k) * HID;
            #pragma unroll
            for (int r = 0; r < 8; r++) s[r] = fmaf(xv, wr[lane + 32 * r], s[r]);
        }

        float q[8], v0[8], v1[8], b1v[8];
        #pragma unroll
        for (int k = 0; k < 8; k++) {
            q[k] = OMB * (s[k] + b0[lane + 32 * k]);
            v0[k] = 0.0f; v1[k] = 0.0f;
            b1v[k] = b1[lane + 32 * k];
        }
        unsigned sp1m[8];
        #pragma unroll
        for (int k = 0; k < 8; k++) sp1m[k] = 0u;

        #pragma unroll 1
        for (int t = 0; t < NUM_STEPS; t++) {
            unsigned act[8];
            #pragma unroll
            for (int k = 0; k < 8; k++) {
                v0[k] = fmaf(BETA, v0[k], q[k]);
                bool sp = (v0[k] >= 1.0f);
                act[k] = __ballot_sync(~0u, sp);
                if (sp) v0[k] = 0.0f;
            }
            float c1[8];
            #pragma unroll
            for (int k = 0; k < 8; k++) c1[k] = b1v[k];
            #pragma unroll
            for (int k = 0; k < 8; k++) {
                unsigned m = act[k];
                while (m) {
                    int j = 32 * k + __ffs(m) - 1;
                    m &= m - 1;
                    const float* wr = g_W1T + (size_t)j * HID;
                    #pragma unroll
                    for (int r = 0; r < 8; r++) c1[r] += wr[lane + 32 * r];
                }
            }
            #pragma unroll
            for (int k = 0; k < 8; k++) {
                v1[k] = fmaf(BETA, v1[k], OMB * c1[k]);
                bool sp = (v1[k] >= 1.0f);
                unsigned b = __ballot_sync(~0u, sp);
                if (t == NUM_STEPS - 1) sp1m[k] = b;
                if (sp) v1[k] = 0.0f;
            }
        }

        #pragma unroll
        for (int k = 0; k < 8; k++)
            actp[lane + 32 * k] = ((sp1m[k] >> lane) & 1u) ? 1.0f : 0.0f;

        float ca = b_out[SPIKE_DIM + lane];
        float cb = b_out[SPIKE_DIM + 32 + lane];
        #pragma unroll
        for (int k = 0; k < 8; k++) {
            unsigned m = sp1m[k];
            while (m) {
                int i = 32 * k + __ffs(m) - 1;
                m &= m - 1;
                ca += g_WcT[(size_t)i * COORD_DIM + lane];
                cb += g_WcT[(size_t)i * COORD_DIM + 32 + lane];
            }
        }
        crdp[lane]      = ca;
        crdp[lane + 32] = cb;
    }
}

// ---------------- launch ----------------
extern "C" void kernel_launch(void* const* d_in, const int* in_sizes, int n_in,
                              void* d_out, int out_size) {
    const float* spikes = (const float*)d_in[0];
    const float* coords = (const float*)d_in[1];
    const float* W0     = (const float*)d_in[2];
    const float* b0     = (const float*)d_in[3];
    const float* W1     = (const float*)d_in[4];
    const float* b1     = (const float*)d_in[5];
    const float* W_out  = (const float*)d_in[6];
    const float* b_out  = (const float*)d_in[7];
    float* out = (float*)d_out;

    k_prep<<<256, 256>>>(W0, W1, b1, W_out);

    cudaFuncSetAttribute(k_gemm, cudaFuncAttributeMaxDynamicSharedMemorySize, GEMM_SMEM);
    k_gemm<<<NBLK, 512, GEMM_SMEM>>>(spikes, coords, b0, b_out, out);

    k_heavy<<<256, 256>>>(spikes, coords, b0, b1, b_out, out);
}